// round 11
// baseline (speedup 1.0000x reference)
#include <cuda_runtime.h>
#include <cuda_fp16.h>
#include <cstdint>

#define BATCH 64
#define DIM   524288
#define PROJ  8192
#define CVAL  4
#define NSHARD 8
#define BCAPS  128   // per-(shard,bucket) capacity; mean 32, Poisson tail ~1e-40

// ----------------------------- device scratch ------------------------------
__device__ __align__(16) unsigned short g_xh[(size_t)DIM * BATCH]; // fp16 xT[d][b], 64 MB
__device__ __align__(16) unsigned g_entries[(size_t)NSHARD * PROJ * BCAPS]; // 32 MB
__device__ int g_cursor[NSHARD * PROJ];                            // 256 KB

// ---------------------------------------------------------------------------
// Kernel 1: transpose x[64][DIM] fp32 -> g_xh[DIM][64] fp16. Also zero cursors.
// grid 8192 x 256 threads; CTA handles 64 d-columns.
// ---------------------------------------------------------------------------
__global__ void __launch_bounds__(256)
transpose_kernel(const float* __restrict__ x) {
    __shared__ float tile[64][65];

    if (blockIdx.x < 16) {  // zero 65536 cursors: 16 CTAs x 256 thr x 4 int4
        #pragma unroll
        for (int k = 0; k < 4; k++) {
            reinterpret_cast<int4*>(g_cursor)[blockIdx.x * 1024 + k * 256 + threadIdx.x] =
                make_int4(0, 0, 0, 0);
        }
    }

    const int d0 = blockIdx.x * 64;
    const int t  = threadIdx.x;

    // Phase 1: coalesced read. Half-warp reads one row chunk (16 x float4 = 64 floats).
    {
        const int col = (t & 15) * 4;
        const int b0  = t >> 4;            // 0..15
        #pragma unroll
        for (int r = 0; r < 4; r++) {
            const int b = r * 16 + b0;
            float4 v = *reinterpret_cast<const float4*>(x + (size_t)b * DIM + d0 + col);
            tile[col + 0][b] = v.x;
            tile[col + 1][b] = v.y;
            tile[col + 2][b] = v.z;
            tile[col + 3][b] = v.w;
        }
    }
    __syncthreads();

    // Phase 2: convert + coalesced write. Thread t: row dd = t>>2, quarter = t&3.
    {
        const int dd   = t >> 2;
        const int part = t & 3;
        __half2 h[8];
        #pragma unroll
        for (int j = 0; j < 8; j++) {
            h[j] = __floats2half2_rn(tile[dd][part * 16 + 2 * j],
                                     tile[dd][part * 16 + 2 * j + 1]);
        }
        uint4* dst = reinterpret_cast<uint4*>(g_xh + (size_t)(d0 + dd) * 64 + part * 16);
        dst[0] = *reinterpret_cast<uint4*>(&h[0]);
        dst[1] = *reinterpret_cast<uint4*>(&h[4]);
    }
}

// ---------------------------------------------------------------------------
// Kernel 2: bucket placement, cursor contention sharded 8x by CTA.
// record = (d << 1) | sign
// ---------------------------------------------------------------------------
__global__ void __launch_bounds__(256)
place_kernel(const int* __restrict__ idx, const int* __restrict__ sgn) {
    const int d     = blockIdx.x * 256 + threadIdx.x;
    const int shard = blockIdx.x & (NSHARD - 1);
    const int4 iv = reinterpret_cast<const int4*>(idx)[d];
    const int4 sv = reinterpret_cast<const int4*>(sgn)[d];
    const unsigned rec = (unsigned)d << 1;
    int* cur = g_cursor + shard * PROJ;
    unsigned* ent = g_entries + (size_t)shard * PROJ * BCAPS;
    int p, pos;
    p = iv.x; pos = atomicAdd(&cur[p], 1);
    if (pos < BCAPS) ent[(size_t)p * BCAPS + pos] = rec | sv.x;
    p = iv.y; pos = atomicAdd(&cur[p], 1);
    if (pos < BCAPS) ent[(size_t)p * BCAPS + pos] = rec | sv.y;
    p = iv.z; pos = atomicAdd(&cur[p], 1);
    if (pos < BCAPS) ent[(size_t)p * BCAPS + pos] = rec | sv.z;
    p = iv.w; pos = atomicAdd(&cur[p], 1);
    if (pos < BCAPS) ent[(size_t)p * BCAPS + pos] = rec | sv.w;
}

// ---------------------------------------------------------------------------
// Kernel 3: gather. One warp per bucket p; 4 entry-groups x 8 lanes per row.
// Each group loads 4 records as ONE uint4, then issues all 4 row loads before
// any FMA -> MLP=4 per thread regardless of (short, sharded) list length.
// Tail: invalid slots clamp to the first (valid) record and use scale 0.
// ---------------------------------------------------------------------------
__device__ __forceinline__ void accum8s(float (&acc)[8], uint4 raw, float s) {
    const float2 f0 = __half22float2(*reinterpret_cast<const __half2*>(&raw.x));
    const float2 f1 = __half22float2(*reinterpret_cast<const __half2*>(&raw.y));
    const float2 f2 = __half22float2(*reinterpret_cast<const __half2*>(&raw.z));
    const float2 f3 = __half22float2(*reinterpret_cast<const __half2*>(&raw.w));
    acc[0] = fmaf(s, f0.x, acc[0]);
    acc[1] = fmaf(s, f0.y, acc[1]);
    acc[2] = fmaf(s, f1.x, acc[2]);
    acc[3] = fmaf(s, f1.y, acc[3]);
    acc[4] = fmaf(s, f2.x, acc[4]);
    acc[5] = fmaf(s, f2.y, acc[5]);
    acc[6] = fmaf(s, f3.x, acc[6]);
    acc[7] = fmaf(s, f3.y, acc[7]);
}

__global__ void __launch_bounds__(256)
gather_kernel(float* __restrict__ out) {
    __shared__ float s_res[64][8];

    const int warp = threadIdx.x >> 5;
    const int lane = threadIdx.x & 31;
    const int p    = blockIdx.x * 8 + warp;
    const int g    = lane >> 3;      // entry group 0..3
    const int sub  = lane & 7;       // batch octet 0..7
    const int suboff = sub << 3;

    const unsigned short* __restrict__ xh = g_xh;

    float acc[8] = {0.f, 0.f, 0.f, 0.f, 0.f, 0.f, 0.f, 0.f};

    #pragma unroll
    for (int s = 0; s < NSHARD; s++) {
        const int count = g_cursor[s * PROJ + p];
        const unsigned* __restrict__ ent =
            g_entries + ((size_t)s * PROJ + p) * BCAPS;

        for (int i = 4 * g; i < count; i += 16) {
            // 4 records in one 16B load (capacity-padded: always in-bounds).
            const uint4 rv = *reinterpret_cast<const uint4*>(ent + i);
            const int rem = count - i;   // >= 1 here

            // Clamp invalid slots to the first (valid) record; scale 0 kills them.
            const unsigned r1 = (rem > 1) ? rv.y : rv.x;
            const unsigned r2 = (rem > 2) ? rv.z : rv.x;
            const unsigned r3 = (rem > 3) ? rv.w : rv.x;

            const float s0 = (rv.x & 1u) ? 1.0f : -1.0f;
            const float s1 = (rem > 1) ? ((r1 & 1u) ? 1.0f : -1.0f) : 0.0f;
            const float s2 = (rem > 2) ? ((r2 & 1u) ? 1.0f : -1.0f) : 0.0f;
            const float s3 = (rem > 3) ? ((r3 & 1u) ? 1.0f : -1.0f) : 0.0f;

            // All 4 row loads issued before any conversion/FMA.
            const uint4 a0 = *reinterpret_cast<const uint4*>(xh + ((size_t)(rv.x >> 1) << 6) + suboff);
            const uint4 a1 = *reinterpret_cast<const uint4*>(xh + ((size_t)(r1   >> 1) << 6) + suboff);
            const uint4 a2 = *reinterpret_cast<const uint4*>(xh + ((size_t)(r2   >> 1) << 6) + suboff);
            const uint4 a3 = *reinterpret_cast<const uint4*>(xh + ((size_t)(r3   >> 1) << 6) + suboff);

            accum8s(acc, a0, s0);
            accum8s(acc, a1, s1);
            accum8s(acc, a2, s2);
            accum8s(acc, a3, s3);
        }
    }

    // Reduce the 4 entry-groups (lanes l, l^8, l^16, l^24 share `sub`).
    #pragma unroll
    for (int k = 0; k < 8; k++) {
        acc[k] += __shfl_xor_sync(0xFFFFFFFFu, acc[k], 8);
        acc[k] += __shfl_xor_sync(0xFFFFFFFFu, acc[k], 16);
    }

    if (lane < 8) {
        #pragma unroll
        for (int k = 0; k < 8; k++)
            s_res[sub * 8 + k][warp] = 0.5f * acc[k];   // scale 1/sqrt(4)
    }
    __syncthreads();

    // Coalesced store: thread t writes float2 of out[b][p0 + part*2].
    {
        const int b    = threadIdx.x >> 2;
        const int part = threadIdx.x & 3;
        float2 v = make_float2(s_res[b][part * 2], s_res[b][part * 2 + 1]);
        *reinterpret_cast<float2*>(out + (size_t)b * PROJ + blockIdx.x * 8 + part * 2) = v;
    }
}

extern "C" void kernel_launch(void* const* d_in, const int* in_sizes, int n_in,
                              void* d_out, int out_size) {
    const float* x   = (const float*)d_in[0];
    const int*   idx = (const int*)d_in[1];
    const int*   sgn = (const int*)d_in[2];
    float*       out = (float*)d_out;

    transpose_kernel<<<DIM / 64, 256>>>(x);
    place_kernel<<<DIM / 256, 256>>>(idx, sgn);
    gather_kernel<<<PROJ / 8, 256>>>(out);
}

// round 12
// speedup vs baseline: 1.1477x; 1.1477x over previous
#include <cuda_runtime.h>
#include <cuda_fp16.h>
#include <cstdint>

#define BATCH 64
#define DIM   524288
#define PROJ  8192
#define CVAL  4
#define NSHARD 8
#define BCAPS  128   // per-(shard,bucket) capacity; mean 32, Poisson tail ~1e-40

// ----------------------------- device scratch ------------------------------
__device__ __align__(16) unsigned short g_xh[(size_t)DIM * BATCH]; // fp16 xT[d][b], 64 MB
__device__ __align__(16) unsigned g_entries[(size_t)NSHARD * PROJ * BCAPS]; // 32 MB
__device__ int g_cursor[NSHARD * PROJ];  // zero-init; gather resets after use

// ---------------------------------------------------------------------------
// Kernel 1 (fused): every CTA transposes its 64 d-columns AND places its own
// 64 d-rows into the sharded bucket lists (threads 0..63, 4 atomics each).
// Atomics are spread uniformly across the whole kernel, sharded 8x.
// ---------------------------------------------------------------------------
__global__ void __launch_bounds__(256)
prep_kernel(const float* __restrict__ x,
            const int* __restrict__ idx, const int* __restrict__ sgn) {
    __shared__ float tile[64][65];

    const int d0 = blockIdx.x * 64;
    const int t  = threadIdx.x;

    // ---- place: threads 0..63, one d each (coalesced int4 reads) ----
    if (t < 64) {
        const int d = d0 + t;
        const int shard = blockIdx.x & (NSHARD - 1);
        const int4 iv = reinterpret_cast<const int4*>(idx)[d];
        const int4 sv = reinterpret_cast<const int4*>(sgn)[d];
        const unsigned rec = (unsigned)d << 1;
        int* cur = g_cursor + shard * PROJ;
        unsigned* ent = g_entries + (size_t)shard * PROJ * BCAPS;
        int p, pos;
        p = iv.x; pos = atomicAdd(&cur[p], 1);
        if (pos < BCAPS) ent[(size_t)p * BCAPS + pos] = rec | sv.x;
        p = iv.y; pos = atomicAdd(&cur[p], 1);
        if (pos < BCAPS) ent[(size_t)p * BCAPS + pos] = rec | sv.y;
        p = iv.z; pos = atomicAdd(&cur[p], 1);
        if (pos < BCAPS) ent[(size_t)p * BCAPS + pos] = rec | sv.z;
        p = iv.w; pos = atomicAdd(&cur[p], 1);
        if (pos < BCAPS) ent[(size_t)p * BCAPS + pos] = rec | sv.w;
    }

    // ---- transpose phase 1: coalesced float4 reads -> smem ----
    {
        const int col = (t & 15) * 4;
        const int b0  = t >> 4;            // 0..15
        #pragma unroll
        for (int r = 0; r < 4; r++) {
            const int b = r * 16 + b0;
            float4 v = *reinterpret_cast<const float4*>(x + (size_t)b * DIM + d0 + col);
            tile[col + 0][b] = v.x;
            tile[col + 1][b] = v.y;
            tile[col + 2][b] = v.z;
            tile[col + 3][b] = v.w;
        }
    }
    __syncthreads();

    // ---- transpose phase 2: convert + coalesced fp16 write ----
    {
        const int dd   = t >> 2;
        const int part = t & 3;
        __half2 h[8];
        #pragma unroll
        for (int j = 0; j < 8; j++) {
            h[j] = __floats2half2_rn(tile[dd][part * 16 + 2 * j],
                                     tile[dd][part * 16 + 2 * j + 1]);
        }
        uint4* dst = reinterpret_cast<uint4*>(g_xh + (size_t)(d0 + dd) * 64 + part * 16);
        dst[0] = *reinterpret_cast<uint4*>(&h[0]);
        dst[1] = *reinterpret_cast<uint4*>(&h[4]);
    }
}

// ---------------------------------------------------------------------------
// Kernel 2: gather (exact R10 inner loop). One warp per bucket p; 4 entry-
// groups x 8 lanes per row. Resets the bucket's 8 shard cursors at the end
// so the next launch (graph replay) sees zeroed counters.
// ---------------------------------------------------------------------------
__device__ __forceinline__ void accum8(float (&acc)[8], uint4 raw, unsigned rec) {
    const float s = (rec & 1u) ? 1.0f : -1.0f;
    const float2 f0 = __half22float2(*reinterpret_cast<const __half2*>(&raw.x));
    const float2 f1 = __half22float2(*reinterpret_cast<const __half2*>(&raw.y));
    const float2 f2 = __half22float2(*reinterpret_cast<const __half2*>(&raw.z));
    const float2 f3 = __half22float2(*reinterpret_cast<const __half2*>(&raw.w));
    acc[0] = fmaf(s, f0.x, acc[0]);
    acc[1] = fmaf(s, f0.y, acc[1]);
    acc[2] = fmaf(s, f1.x, acc[2]);
    acc[3] = fmaf(s, f1.y, acc[3]);
    acc[4] = fmaf(s, f2.x, acc[4]);
    acc[5] = fmaf(s, f2.y, acc[5]);
    acc[6] = fmaf(s, f3.x, acc[6]);
    acc[7] = fmaf(s, f3.y, acc[7]);
}

__global__ void __launch_bounds__(256)
gather_kernel(float* __restrict__ out) {
    __shared__ float s_res[64][8];

    const int warp = threadIdx.x >> 5;
    const int lane = threadIdx.x & 31;
    const int p    = blockIdx.x * 8 + warp;
    const int g    = lane >> 3;      // entry group 0..3
    const int sub  = lane & 7;       // batch octet 0..7

    const unsigned short* __restrict__ xh = g_xh;

    float acc[8] = {0.f, 0.f, 0.f, 0.f, 0.f, 0.f, 0.f, 0.f};

    #pragma unroll
    for (int s = 0; s < NSHARD; s++) {
        int count = g_cursor[s * PROJ + p];
        count = (count < BCAPS) ? count : BCAPS;
        const unsigned* __restrict__ ent =
            g_entries + ((size_t)s * PROJ + p) * BCAPS;
        for (int i = g; i < count; i += 4) {
            const unsigned r = ent[i];
            const uint4 a = *reinterpret_cast<const uint4*>(
                xh + ((size_t)(r >> 1) << 6) + (sub << 3));
            accum8(acc, a, r);
        }
    }

    // Reset this bucket's shard cursors for the next launch.
    if (lane < NSHARD) g_cursor[lane * PROJ + p] = 0;

    // Reduce the 4 entry-groups (lanes l, l^8, l^16, l^24 share `sub`).
    #pragma unroll
    for (int k = 0; k < 8; k++) {
        acc[k] += __shfl_xor_sync(0xFFFFFFFFu, acc[k], 8);
        acc[k] += __shfl_xor_sync(0xFFFFFFFFu, acc[k], 16);
    }

    if (lane < 8) {
        #pragma unroll
        for (int k = 0; k < 8; k++)
            s_res[sub * 8 + k][warp] = 0.5f * acc[k];   // scale 1/sqrt(4)
    }
    __syncthreads();

    // Coalesced store: thread t writes float2 of out[b][p0 + part*2].
    {
        const int b    = threadIdx.x >> 2;
        const int part = threadIdx.x & 3;
        float2 v = make_float2(s_res[b][part * 2], s_res[b][part * 2 + 1]);
        *reinterpret_cast<float2*>(out + (size_t)b * PROJ + blockIdx.x * 8 + part * 2) = v;
    }
}

extern "C" void kernel_launch(void* const* d_in, const int* in_sizes, int n_in,
                              void* d_out, int out_size) {
    const float* x   = (const float*)d_in[0];
    const int*   idx = (const int*)d_in[1];
    const int*   sgn = (const int*)d_in[2];
    float*       out = (float*)d_out;

    prep_kernel<<<DIM / 64, 256>>>(x, idx, sgn);
    gather_kernel<<<PROJ / 8, 256>>>(out);
}